// round 1
// baseline (speedup 1.0000x reference)
#include <cuda_runtime.h>
#include <math.h>

#define B_  4
#define S_  2048
#define SV_ 50
#define E_  1024

// ---------------- scratch (device globals; no allocation allowed) ----------
__device__ float g_q [B_*S_*E_];
__device__ float g_k [B_*S_*E_];
__device__ float g_q2[B_*S_*E_];
__device__ float g_k2[B_*S_*E_];
__device__ float g_v [B_*SV_*E_];
__device__ float g_vq[B_*S_*SV_];
__device__ float g_vk[B_*S_*SV_];
__device__ float g_cs [B_*E_];
__device__ float g_cs2[B_*E_];

// ---------------- generic guarded batched SGEMM ----------------------------
// C[b] = alpha * op(A[b]) @ op(B[b]) (+ beta*C[b]) (+ bias[b][n])
// A: [M,K] row-major (optionally tanh applied elementwise)
// B: NN -> [K,N] row-major ; NT -> [N,K] row-major (computes A @ B^T)
// C: [M,N] row-major
template<bool TANH_A, bool TRANS_B, bool BETA, bool BIAS>
__global__ __launch_bounds__(256, 2)
void gemm_k(const float* __restrict__ A, const float* __restrict__ Bm,
            float* __restrict__ C, const float* __restrict__ bias,
            int M, int N, int K,
            long long sA, long long sB, long long sC, long long sBias,
            float alpha, float beta)
{
    constexpr int BM = 128, BN = 128, BK = 16;
    __shared__ float As[2][BK][BM + 4];
    __shared__ float Bs[2][BK][BN + 4];

    A  += (long long)blockIdx.z * sA;
    Bm += (long long)blockIdx.z * sB;
    C  += (long long)blockIdx.z * sC;
    const float* biasp = nullptr;
    if (BIAS) biasp = bias + (long long)blockIdx.z * sBias;

    const int tid  = threadIdx.x;
    const int warp = tid >> 5, lane = tid & 31;
    const int wr = warp & 3, wc = warp >> 2;   // 4x2 warp grid (32x64 each)
    const int lr = lane >> 3, lc = lane & 7;   // 4x8 lanes (8x8 each)
    const int m0 = wr * 32 + lr * 8;
    const int n0 = wc * 64 + lc * 8;

    const int bm = blockIdx.y * BM;
    const int bn = blockIdx.x * BN;

    float acc[8][8];
#pragma unroll
    for (int i = 0; i < 8; i++)
#pragma unroll
        for (int j = 0; j < 8; j++) acc[i][j] = 0.f;

    const int nt = (K + BK - 1) / BK;
    float ra[8], rb[8];

    auto loadA = [&](int kt) {
#pragma unroll
        for (int i = 0; i < 8; i++) {
            int idx = i * 256 + tid;
            int row = idx >> 4, kk = idx & 15;
            int gm = bm + row, gk = kt * BK + kk;
            float v = 0.f;
            if (gm < M && gk < K) v = A[(long long)gm * K + gk];
            if (TANH_A) v = tanhf(v);
            ra[i] = v;
        }
    };
    auto loadB = [&](int kt) {
#pragma unroll
        for (int i = 0; i < 8; i++) {
            int idx = i * 256 + tid;
            float v = 0.f;
            if (!TRANS_B) {
                int kk = idx >> 7, n = idx & 127;
                int gk = kt * BK + kk, gn = bn + n;
                if (gk < K && gn < N) v = Bm[(long long)gk * N + gn];
            } else {
                int n = idx >> 4, kk = idx & 15;
                int gn = bn + n, gk = kt * BK + kk;
                if (gn < N && gk < K) v = Bm[(long long)gn * K + gk];
            }
            rb[i] = v;
        }
    };
    auto storeA = [&](int buf) {
#pragma unroll
        for (int i = 0; i < 8; i++) {
            int idx = i * 256 + tid;
            As[buf][idx & 15][idx >> 4] = ra[i];
        }
    };
    auto storeB = [&](int buf) {
#pragma unroll
        for (int i = 0; i < 8; i++) {
            int idx = i * 256 + tid;
            if (!TRANS_B) Bs[buf][idx >> 7][idx & 127] = rb[i];
            else          Bs[buf][idx & 15][idx >> 4]  = rb[i];
        }
    };

    loadA(0); loadB(0); storeA(0); storeB(0);
    __syncthreads();

    for (int kt = 0; kt < nt; ++kt) {
        const int cur = kt & 1;
        if (kt + 1 < nt) { loadA(kt + 1); loadB(kt + 1); }
#pragma unroll
        for (int kk = 0; kk < BK; ++kk) {
            float af[8], bf[8];
#pragma unroll
            for (int i = 0; i < 8; i++) af[i] = As[cur][kk][m0 + i];
#pragma unroll
            for (int j = 0; j < 8; j++) bf[j] = Bs[cur][kk][n0 + j];
#pragma unroll
            for (int i = 0; i < 8; i++)
#pragma unroll
                for (int j = 0; j < 8; j++) acc[i][j] += af[i] * bf[j];
        }
        if (kt + 1 < nt) { storeA(cur ^ 1); storeB(cur ^ 1); }
        __syncthreads();
    }

#pragma unroll
    for (int i = 0; i < 8; i++) {
        int gm = bm + m0 + i;
        if (gm < M) {
#pragma unroll
            for (int j = 0; j < 8; j++) {
                int gn = bn + n0 + j;
                if (gn < N) {
                    float v = alpha * acc[i][j];
                    if (BETA) v += beta * C[(long long)gm * N + gn];
                    if (BIAS) v += biasp[gn];
                    C[(long long)gm * N + gn] = v;
                }
            }
        }
    }
}

// ---------------- softmax over rows (in place) ------------------------------
__global__ void softmax_kernel(float* __restrict__ x, int cols)
{
    long long row = blockIdx.x;
    float* p = x + row * (long long)cols;
    __shared__ float red[256];
    int t = threadIdx.x;

    float mx = -INFINITY;
    for (int c = t; c < cols; c += 256) mx = fmaxf(mx, p[c]);
    red[t] = mx; __syncthreads();
    for (int s = 128; s > 0; s >>= 1) {
        if (t < s) red[t] = fmaxf(red[t], red[t + s]);
        __syncthreads();
    }
    mx = red[0]; __syncthreads();

    float sum = 0.f;
    for (int c = t; c < cols; c += 256) {
        float e = expf(p[c] - mx);
        p[c] = e;
        sum += e;
    }
    red[t] = sum; __syncthreads();
    for (int s = 128; s > 0; s >>= 1) {
        if (t < s) red[t] += red[t + s];
        __syncthreads();
    }
    float inv = 1.f / red[0];
    for (int c = t; c < cols; c += 256) p[c] *= inv;
}

// ---------------- column sum: out[b,e] = sum_t x[b,t,e] ---------------------
__global__ void colsum_kernel(const float* __restrict__ x, float* __restrict__ out,
                              int T, int E)
{
    int e = blockIdx.x * blockDim.x + threadIdx.x;
    int b = blockIdx.y;
    const float* p = x + (long long)b * T * E + e;
    float s = 0.f;
    for (int t = 0; t < T; t++) s += p[(long long)t * E];
    out[(long long)b * E + e] = s;
}

// ---------------- host launcher ---------------------------------------------
extern "C" void kernel_launch(void* const* d_in, const int* in_sizes, int n_in,
                              void* d_out, int out_size)
{
    const float* Q    = (const float*)d_in[0];
    const float* K    = (const float*)d_in[1];
    const float* V    = (const float*)d_in[2];
    const float* W_Q  = (const float*)d_in[3];
    const float* W_K  = (const float*)d_in[4];
    const float* W_v  = (const float*)d_in[5];
    const float* W_vq = (const float*)d_in[6];
    const float* W_vk = (const float*)d_in[7];

    float* out  = (float*)d_out;
    float* outQ = out;                                  // [B,S,E]
    float* outK = out + (long long)B_ * S_ * E_;        // [B,S,E]
    float* f    = out + 2ll * B_ * S_ * E_;             // [B,S,S]

    float *q, *k, *v, *q2, *k2, *vq, *vk, *cs, *cs2;
    cudaGetSymbolAddress((void**)&q,   g_q);
    cudaGetSymbolAddress((void**)&k,   g_k);
    cudaGetSymbolAddress((void**)&v,   g_v);
    cudaGetSymbolAddress((void**)&q2,  g_q2);
    cudaGetSymbolAddress((void**)&k2,  g_k2);
    cudaGetSymbolAddress((void**)&vq,  g_vq);
    cudaGetSymbolAddress((void**)&vk,  g_vk);
    cudaGetSymbolAddress((void**)&cs,  g_cs);
    cudaGetSymbolAddress((void**)&cs2, g_cs2);

    const float inv = 1.0f / 32.0f;   // 1/sqrt(1024)
    const long long sQE = (long long)S_ * E_;
    const long long sSS = (long long)S_ * S_;
    const long long sSV = (long long)S_ * SV_;
    dim3 blk(256);

    // projections: q = tanh(Q)@W_Q, k = tanh(K)@W_K  (M=B*S flattened, W shared)
    gemm_k<true,false,false,false><<<dim3(8,64,1),blk>>>(Q, W_Q, q, nullptr,
        B_*S_, E_, E_, 0,0,0,0, 1.f, 0.f);
    gemm_k<true,false,false,false><<<dim3(8,64,1),blk>>>(K, W_K, k, nullptr,
        B_*S_, E_, E_, 0,0,0,0, 1.f, 0.f);
    // v = tanh(V)@W_v  (M = B*SV = 200)
    gemm_k<true,false,false,false><<<dim3(8,2,1),blk>>>(V, W_v, v, nullptr,
        B_*SV_, E_, E_, 0,0,0,0, 1.f, 0.f);

    // scores -> f region of d_out: f = (q @ k^T)/32, then softmax in place
    gemm_k<false,true,false,false><<<dim3(16,16,B_),blk>>>(q, k, f, nullptr,
        S_, S_, E_, sQE, sQE, sSS, 0, inv, 0.f);
    softmax_kernel<<<B_*S_, 256>>>(f, S_);

    // vq = q@v^T/32, vk = k@v^T/32   [B,S,SV]
    gemm_k<false,true,false,false><<<dim3(1,16,B_),blk>>>(q, v, vq, nullptr,
        S_, SV_, E_, sQE, (long long)SV_*E_, sSV, 0, inv, 0.f);
    gemm_k<false,true,false,false><<<dim3(1,16,B_),blk>>>(k, v, vk, nullptr,
        S_, SV_, E_, sQE, (long long)SV_*E_, sSV, 0, inv, 0.f);

    // colsum_k[b,e] = sum_t k[b,t,e]   (g@x = colsum(x) - f@x)
    colsum_kernel<<<dim3(E_/256, B_), 256>>>(k, cs, S_, E_);

    // q2 = vq@W_vq ; k2 = vk@W_vk + colsum_k
    gemm_k<false,false,false,false><<<dim3(8,16,B_),blk>>>(vq, W_vq, q2, nullptr,
        S_, E_, SV_, sSV, 0, sQE, 0, 1.f, 0.f);
    gemm_k<false,false,false,true><<<dim3(8,16,B_),blk>>>(vk, W_vk, k2, cs,
        S_, E_, SV_, sSV, 0, sQE, E_, 1.f, 0.f);

    // q2 += f@q ; k2 += -f@k
    gemm_k<false,false,true,false><<<dim3(8,16,B_),blk>>>(f, q, q2, nullptr,
        S_, E_, S_, sSS, sQE, sQE, 0, 1.f, 1.f);
    gemm_k<false,false,true,false><<<dim3(8,16,B_),blk>>>(f, k, k2, nullptr,
        S_, E_, S_, sSS, sQE, sQE, 0, -1.f, 1.f);

    colsum_kernel<<<dim3(E_/256, B_), 256>>>(k2, cs2, S_, E_);

    // Q_out = f@q2 ; K_out = colsum_k2 - f@k2
    gemm_k<false,false,false,false><<<dim3(8,16,B_),blk>>>(f, q2, outQ, nullptr,
        S_, E_, S_, sSS, sQE, sQE, 0, 1.f, 0.f);
    gemm_k<false,false,false,true><<<dim3(8,16,B_),blk>>>(f, k2, outK, cs2,
        S_, E_, S_, sSS, sQE, sQE, E_, -1.f, 0.f);

    (void)in_sizes; (void)n_in; (void)out_size;
}